// round 8
// baseline (speedup 1.0000x reference)
#include <cuda_runtime.h>
#include <cuda_fp16.h>
#include <cstdint>

#define Z_STRIDE 272                     // 128 fp16 + 16B pad; 272 % 128 == 16 -> conflict-free ldmatrix
#define SMEM_TOTAL (256 * Z_STRIDE)      // 69632 B -> 3 CTAs/SM

__device__ uint32_t g_wfrag[32768];      // mma.sync A fragments: [wb(8)][lane(32)][fi(128)]

__device__ __forceinline__ uint32_t s2u(const void* p){
    uint32_t a;
    asm("{ .reg .u64 t; cvta.to.shared.u64 t, %1; cvt.u32.u64 %0, t; }" : "=r"(a) : "l"(p));
    return a;
}

// ---------------- weight prep (A fragments for mma.sync) ----------------
__global__ void __launch_bounds__(256) prep_weights(const float* __restrict__ cw){
    const int idx = blockIdx.x * 256 + threadIdx.x;      // 32768
    int wb = idx >> 12;
    int ln = (idx >> 7) & 31;
    int fi = idx & 127;
    int kt = fi >> 3, mt = (fi >> 2) & 1, j = fi & 3;
    int o = wb * 32 + mt * 16 + (ln >> 2) + (j & 1) * 8;
    int c = kt * 16 + (ln & 3) * 2 + (j >> 1) * 8;
    float2 wv = *(const float2*)(cw + o * 256 + c);
    __half2 hw = __floats2half2_rn(wv.x, wv.y);
    g_wfrag[idx] = *(uint32_t*)&hw;
}

// ---------------- fused kernel: one CTA per (b, h, w-half) ----------------
__global__ void __launch_bounds__(256, 3)
fused_ln_conv_relu(const float* __restrict__ x, const float* __restrict__ y,
                   const float* __restrict__ lnw, const float* __restrict__ lnb,
                   float* __restrict__ out)
{
    extern __shared__ __align__(128) char smem[];
    const uint32_t su = s2u(smem);
    const int tid = threadIdx.x, wid = tid >> 5, lane = tid & 31;
    const int bid = blockIdx.x;
    const int whalf = bid & 1;
    const int h = (bid >> 1) & 255;
    const int b = bid >> 9;
    const size_t base_bh = ((size_t)b << 24) + ((size_t)h << 8);

    // LN params only for this CTA's w-half (w = whalf*128 + 4*lane + j)
    const float4 lw = *(const float4*)(lnw + whalf * 128 + 4 * lane);
    const float4 lb = *(const float4*)(lnb + whalf * 128 + 4 * lane);

    // ---- phase 1: residual add + LayerNorm -> Z fp16 [256c][128w-half] ----
    {
        const int wh = whalf * 128;
        #pragma unroll 2
        for (int r = 0; r < 32; r++) {
            const int c = wid * 32 + r;
            const float* px = x + base_bh + ((size_t)c << 16) + 4 * lane;
            const float* py = y + base_bh + ((size_t)c << 16) + 4 * lane;
            float4 xa = *(const float4*)px;
            float4 xb = *(const float4*)(px + 128);
            float4 ya = *(const float4*)py;
            float4 yb = *(const float4*)(py + 128);
            float v0 = xa.x + ya.x, v1 = xa.y + ya.y, v2 = xa.z + ya.z, v3 = xa.w + ya.w;
            float v4 = xb.x + yb.x, v5 = xb.y + yb.y, v6 = xb.z + yb.z, v7 = xb.w + yb.w;
            float s = v0+v1+v2+v3+v4+v5+v6+v7;
            float q = v0*v0+v1*v1+v2*v2+v3*v3+v4*v4+v5*v5+v6*v6+v7*v7;
            #pragma unroll
            for (int o_ = 16; o_; o_ >>= 1) {
                s += __shfl_xor_sync(0xFFFFFFFFu, s, o_);
                q += __shfl_xor_sync(0xFFFFFFFFu, q, o_);
            }
            const float mean = s * (1.0f / 256.0f);
            const float rstd = rsqrtf(q * (1.0f / 256.0f) - mean * mean + 1e-5f);
            // pick this CTA's half
            float u0 = wh ? v4 : v0, u1 = wh ? v5 : v1;
            float u2 = wh ? v6 : v2, u3 = wh ? v7 : v3;
            __half2 h01 = __floats2half2_rn((u0-mean)*rstd*lw.x + lb.x, (u1-mean)*rstd*lw.y + lb.y);
            __half2 h23 = __floats2half2_rn((u2-mean)*rstd*lw.z + lb.z, (u3-mean)*rstd*lw.w + lb.w);
            *(uint2*)(smem + c * Z_STRIDE + 8 * lane) =
                make_uint2(*(uint32_t*)&h01, *(uint32_t*)&h23);
        }
    }
    __syncthreads();

    // ---- phase 2: GEMM D[o, w-half] = sum_c W[o,c] * Z[c,w], mma.sync m16n8k16 ----
    const uint4* wf = (const uint4*)g_wfrag + (wid * 32 + lane) * 32;
    const int g = lane >> 2, t = lane & 3;
    const uint32_t krow_off = ((uint32_t)((lane >> 3) & 1)) * 8 + (lane & 7);
    const uint32_t ncol_off = ((uint32_t)(lane >> 4)) * 8;

    #pragma unroll 1
    for (int wc = 0; wc < 4; wc++) {                 // w-chunks of 32 within the 128 half
        float acc[2][4][4] = {};
        #pragma unroll 2
        for (int kt = 0; kt < 16; kt++) {
            uint32_t bf[4][2];
            #pragma unroll
            for (int qq = 0; qq < 2; qq++) {
                uint32_t addr = su + (kt * 16 + krow_off) * Z_STRIDE
                                   + (uint32_t)(wc * 32 + qq * 16) * 2 + ncol_off * 2;
                asm volatile("ldmatrix.sync.aligned.m8n8.x4.trans.shared.b16 {%0,%1,%2,%3}, [%4];"
                             : "=r"(bf[2*qq][0]), "=r"(bf[2*qq][1]),
                               "=r"(bf[2*qq+1][0]), "=r"(bf[2*qq+1][1])
                             : "r"(addr));
            }
            uint4 a0 = __ldg(wf + kt * 2);
            uint4 a1 = __ldg(wf + kt * 2 + 1);
            #pragma unroll
            for (int nt = 0; nt < 4; nt++) {
                asm volatile(
                    "mma.sync.aligned.m16n8k16.row.col.f32.f16.f16.f32 "
                    "{%0,%1,%2,%3}, {%4,%5,%6,%7}, {%8,%9}, {%0,%1,%2,%3};"
                    : "+f"(acc[0][nt][0]), "+f"(acc[0][nt][1]), "+f"(acc[0][nt][2]), "+f"(acc[0][nt][3])
                    : "r"(a0.x), "r"(a0.y), "r"(a0.z), "r"(a0.w),
                      "r"(bf[nt][0]), "r"(bf[nt][1]));
                asm volatile(
                    "mma.sync.aligned.m16n8k16.row.col.f32.f16.f16.f32 "
                    "{%0,%1,%2,%3}, {%4,%5,%6,%7}, {%8,%9}, {%0,%1,%2,%3};"
                    : "+f"(acc[1][nt][0]), "+f"(acc[1][nt][1]), "+f"(acc[1][nt][2]), "+f"(acc[1][nt][3])
                    : "r"(a1.x), "r"(a1.y), "r"(a1.z), "r"(a1.w),
                      "r"(bf[nt][0]), "r"(bf[nt][1]));
            }
        }
        // store this w-chunk with ReLU, direct from fragments (evict-first)
        #pragma unroll
        for (int mt = 0; mt < 2; mt++) {
            #pragma unroll
            for (int nt = 0; nt < 4; nt++) {
                const int o = wid * 32 + mt * 16 + g;
                const int w = whalf * 128 + wc * 32 + nt * 8 + t * 2;
                float* p0 = out + ((size_t)b << 24) + ((size_t)o << 16) + ((size_t)h << 8) + w;
                float2 v0 = make_float2(fmaxf(acc[mt][nt][0], 0.f), fmaxf(acc[mt][nt][1], 0.f));
                float2 v1 = make_float2(fmaxf(acc[mt][nt][2], 0.f), fmaxf(acc[mt][nt][3], 0.f));
                __stcs((float2*)p0, v0);
                __stcs((float2*)(p0 + (8 << 16)), v1);
            }
        }
    }
}

extern "C" void kernel_launch(void* const* d_in, const int* in_sizes, int n_in,
                              void* d_out, int out_size) {
    (void)in_sizes; (void)n_in; (void)out_size;
    const float* x   = (const float*)d_in[0];
    const float* y   = (const float*)d_in[1];
    const float* lnw = (const float*)d_in[2];
    const float* lnb = (const float*)d_in[3];
    const float* cw  = (const float*)d_in[4];
    float* out = (float*)d_out;

    cudaFuncSetAttribute(fused_ln_conv_relu, cudaFuncAttributeMaxDynamicSharedMemorySize, SMEM_TOTAL);

    prep_weights<<<128, 256>>>(cw);
    fused_ln_conv_relu<<<2048, 256, SMEM_TOTAL>>>(x, y, lnw, lnb, out);
}

// round 10
// speedup vs baseline: 1.4106x; 1.4106x over previous
#include <cuda_runtime.h>
#include <cuda_fp16.h>
#include <cstdint>

#define Z_STRIDE 528                      // 256 fp16 + 16B pad -> conflict-free ldmatrix
#define SMEM_TOTAL (256 * Z_STRIDE)       // 135168 B, 1 CTA/SM

__device__ uint32_t g_wfrag[32768];       // A fragments: [wb(8)][lane(32)][fi(128)]

__device__ __forceinline__ uint32_t s2u(const void* p){
    uint32_t a;
    asm("{ .reg .u64 t; cvta.to.shared.u64 t, %1; cvt.u32.u64 %0, t; }" : "=r"(a) : "l"(p));
    return a;
}

// ---------------- weight prep (A fragments for mma.sync) ----------------
__global__ void __launch_bounds__(256) prep_weights(const float* __restrict__ cw){
    const int idx = blockIdx.x * 256 + threadIdx.x;      // 32768
    int wb = idx >> 12;
    int ln = (idx >> 7) & 31;
    int fi = idx & 127;
    int kt = fi >> 3, mt = (fi >> 2) & 1, j = fi & 3;
    int o = wb * 32 + mt * 16 + (ln >> 2) + (j & 1) * 8;
    int c = kt * 16 + (ln & 3) * 2 + (j >> 1) * 8;
    float2 wv = *(const float2*)(cw + o * 256 + c);
    __half2 hw = __floats2half2_rn(wv.x, wv.y);
    g_wfrag[idx] = *(uint32_t*)&hw;
}

// ---------------- fused kernel: one 512-thread CTA per (b, h) ----------------
__global__ void __launch_bounds__(512, 1)
fused_ln_conv_relu(const float* __restrict__ x, const float* __restrict__ y,
                   const float* __restrict__ lnw, const float* __restrict__ lnb,
                   float* __restrict__ out)
{
    extern __shared__ __align__(128) char smem[];
    const uint32_t su = s2u(smem);
    const int tid = threadIdx.x, wid = tid >> 5, lane = tid & 31;
    const int b = blockIdx.x >> 8, h = blockIdx.x & 255;
    const size_t base_bh = ((size_t)b << 24) + ((size_t)h << 8);

    const float4 lwa = *(const float4*)(lnw + 4 * lane);
    const float4 lwb = *(const float4*)(lnw + 128 + 4 * lane);
    const float4 lba = *(const float4*)(lnb + 4 * lane);
    const float4 lbb = *(const float4*)(lnb + 128 + 4 * lane);

    // ---- phase 1: residual add + LayerNorm -> Z fp16 [256c][256w], 16 rows/warp ----
    {
        #pragma unroll 4
        for (int r = 0; r < 16; r++) {
            const int c = wid * 16 + r;
            const float* px = x + base_bh + ((size_t)c << 16) + 4 * lane;
            const float* py = y + base_bh + ((size_t)c << 16) + 4 * lane;
            float4 xa = *(const float4*)px;
            float4 xb = *(const float4*)(px + 128);
            float4 ya = *(const float4*)py;
            float4 yb = *(const float4*)(py + 128);
            float v0 = xa.x + ya.x, v1 = xa.y + ya.y, v2 = xa.z + ya.z, v3 = xa.w + ya.w;
            float v4 = xb.x + yb.x, v5 = xb.y + yb.y, v6 = xb.z + yb.z, v7 = xb.w + yb.w;
            float s = v0+v1+v2+v3+v4+v5+v6+v7;
            float q = v0*v0+v1*v1+v2*v2+v3*v3+v4*v4+v5*v5+v6*v6+v7*v7;
            #pragma unroll
            for (int o_ = 16; o_; o_ >>= 1) {
                s += __shfl_xor_sync(0xFFFFFFFFu, s, o_);
                q += __shfl_xor_sync(0xFFFFFFFFu, q, o_);
            }
            const float mean = s * (1.0f / 256.0f);
            const float rstd = rsqrtf(q * (1.0f / 256.0f) - mean * mean + 1e-5f);
            __half2 h01 = __floats2half2_rn((v0-mean)*rstd*lwa.x + lba.x, (v1-mean)*rstd*lwa.y + lba.y);
            __half2 h23 = __floats2half2_rn((v2-mean)*rstd*lwa.z + lba.z, (v3-mean)*rstd*lwa.w + lba.w);
            __half2 h45 = __floats2half2_rn((v4-mean)*rstd*lwb.x + lbb.x, (v5-mean)*rstd*lwb.y + lbb.y);
            __half2 h67 = __floats2half2_rn((v6-mean)*rstd*lwb.z + lbb.z, (v7-mean)*rstd*lwb.w + lbb.w);
            char* zr = smem + c * Z_STRIDE;
            *(uint2*)(zr + 8 * lane)       = make_uint2(*(uint32_t*)&h01, *(uint32_t*)&h23);
            *(uint2*)(zr + 256 + 8 * lane) = make_uint2(*(uint32_t*)&h45, *(uint32_t*)&h67);
        }
    }
    __syncthreads();

    // ---- phase 2: GEMM D[o,w] = sum_c W[o,c] * Z[c,w]; warp owns 16 o-rows ----
    // A fragments: warp wid -> weight block wb = wid>>1, half mt = wid&1
    const uint4* wf = (const uint4*)g_wfrag + (((wid >> 1) * 32 + lane) * 32) + (wid & 1);
    const int g = lane >> 2, t = lane & 3;
    const uint32_t krow_off = ((uint32_t)((lane >> 3) & 1)) * 8 + (lane & 7);
    const uint32_t ncol_off = ((uint32_t)(lane >> 4)) * 8;
    const int o_row = wid * 16 + g;
    float* outp = out + ((size_t)b << 24) + ((size_t)o_row << 16) + ((size_t)h << 8);

    #pragma unroll 1
    for (int wc = 0; wc < 4; wc++) {                 // w-chunks of 64
        float acc[8][4] = {};
        #pragma unroll 2
        for (int kt = 0; kt < 16; kt++) {
            uint4 a = __ldg(wf + kt * 2);
            uint32_t bf[8][2];
            #pragma unroll
            for (int qq = 0; qq < 4; qq++) {
                uint32_t addr = su + (kt * 16 + krow_off) * Z_STRIDE
                                   + (uint32_t)(wc * 64 + qq * 16) * 2 + ncol_off * 2;
                asm volatile("ldmatrix.sync.aligned.m8n8.x4.trans.shared.b16 {%0,%1,%2,%3}, [%4];"
                             : "=r"(bf[2*qq][0]), "=r"(bf[2*qq][1]),
                               "=r"(bf[2*qq+1][0]), "=r"(bf[2*qq+1][1])
                             : "r"(addr));
            }
            #pragma unroll
            for (int nt = 0; nt < 8; nt++) {
                asm volatile(
                    "mma.sync.aligned.m16n8k16.row.col.f32.f16.f16.f32 "
                    "{%0,%1,%2,%3}, {%4,%5,%6,%7}, {%8,%9}, {%0,%1,%2,%3};"
                    : "+f"(acc[nt][0]), "+f"(acc[nt][1]), "+f"(acc[nt][2]), "+f"(acc[nt][3])
                    : "r"(a.x), "r"(a.y), "r"(a.z), "r"(a.w),
                      "r"(bf[nt][0]), "r"(bf[nt][1]));
            }
        }
        // store this w-chunk with ReLU, direct from fragments (streaming)
        #pragma unroll
        for (int nt = 0; nt < 8; nt++) {
            const int w = wc * 64 + nt * 8 + t * 2;
            float* p0 = outp + w;
            float2 v0 = make_float2(fmaxf(acc[nt][0], 0.f), fmaxf(acc[nt][1], 0.f));
            float2 v1 = make_float2(fmaxf(acc[nt][2], 0.f), fmaxf(acc[nt][3], 0.f));
            __stcs((float2*)p0, v0);
            __stcs((float2*)(p0 + (8 << 16)), v1);   // o_row + 8
        }
    }
}

extern "C" void kernel_launch(void* const* d_in, const int* in_sizes, int n_in,
                              void* d_out, int out_size) {
    (void)in_sizes; (void)n_in; (void)out_size;
    const float* x   = (const float*)d_in[0];
    const float* y   = (const float*)d_in[1];
    const float* lnw = (const float*)d_in[2];
    const float* lnb = (const float*)d_in[3];
    const float* cw  = (const float*)d_in[4];
    float* out = (float*)d_out;

    cudaFuncSetAttribute(fused_ln_conv_relu, cudaFuncAttributeMaxDynamicSharedMemorySize, SMEM_TOTAL);

    prep_weights<<<128, 256>>>(cw);
    fused_ln_conv_relu<<<1024, 512, SMEM_TOTAL>>>(x, y, lnw, lnb, out);
}